// round 5
// baseline (speedup 1.0000x reference)
#include <cuda_runtime.h>
#include <cstdint>

#define N_NODES 100000
#define N_EDGES 1600000
#define DD 64

typedef unsigned long long u64;

// ------------------- scratch (static device globals; no allocation) -------------------
__device__ float g_x1[(size_t)N_NODES * DD];        // x@W1^T+b1
__device__ float g_x3[(size_t)N_NODES * DD];        // x@W3^T+b3
__device__ float g_x24[(size_t)N_NODES * 2 * DD];   // per node: [x2 row | x4 row]
__device__ float g_y[(size_t)N_NODES * DD];         // x1 + aggregated (pre-BN node)
__device__ float g_sums[(size_t)N_NODES * DD];      // scatter-add accumulator
__device__ float g_cnt[N_NODES];                    // per-src edge counts
__device__ float g_t[(size_t)N_EDGES * DD];         // pre-BN edge tensor (409.6 MB)
__device__ float g_WtN[64 * 256];                   // k-major stacked [W1|W2|W3|W4]
__device__ float g_bN[256];
__device__ float g_WtE[64 * 64];                    // k-major We
__device__ float g_nstat[128];                      // node: sum[64], ssq[64]
__device__ float g_estat[128];                      // edge: sum[64], ssq[64]

// ------------------- helpers -------------------
__device__ __forceinline__ u64 pack2(float lo, float hi) {
    u64 r; unsigned a = __float_as_uint(lo), b = __float_as_uint(hi);
    asm("mov.b64 %0, {%1,%2};" : "=l"(r) : "r"(a), "r"(b));
    return r;
}
__device__ __forceinline__ u64 bcast2(float v) {
    u64 r; unsigned a = __float_as_uint(v);
    asm("mov.b64 %0, {%1,%1};" : "=l"(r) : "r"(a));
    return r;
}
__device__ __forceinline__ void fma2(u64& d, u64 a, u64 b) {
    asm("fma.rn.f32x2 %0, %1, %2, %0;" : "+l"(d) : "l"(a), "l"(b));
}
__device__ __forceinline__ float2 unpack2(u64 v) {
    unsigned lo, hi;
    asm("mov.b64 {%0,%1}, %2;" : "=r"(lo), "=r"(hi) : "l"(v));
    return make_float2(__uint_as_float(lo), __uint_as_float(hi));
}
__device__ __forceinline__ float sigmoidf(float x) { return 1.0f / (1.0f + __expf(-x)); }

__device__ __forceinline__ unsigned sm2u(const void* p) {
    return (unsigned)__cvta_generic_to_shared(p);
}
__device__ __forceinline__ u64 mkpolicy_evict_first() {
    u64 p;
    asm("createpolicy.fractional.L2::evict_first.b64 %0, 1.0;" : "=l"(p));
    return p;
}
__device__ __forceinline__ void cpa16(unsigned s, const void* g) {
    asm volatile("cp.async.cg.shared.global [%0], [%1], 16;" :: "r"(s), "l"(g));
}
__device__ __forceinline__ void cpa16_pol(unsigned s, const void* g, u64 pol) {
    asm volatile("cp.async.cg.shared.global.L2::cache_hint [%0], [%1], 16, %2;"
                 :: "r"(s), "l"(g), "l"(pol));
}
__device__ __forceinline__ void cpa_commit() {
    asm volatile("cp.async.commit_group;");
}
__device__ __forceinline__ void cpa_wait0() {
    asm volatile("cp.async.wait_group 0;");
}
__device__ __forceinline__ void red4(float* p, float a, float b, float c, float d) {
    asm volatile("red.global.add.v4.f32 [%0], {%1,%2,%3,%4};"
                 :: "l"(p), "f"(a), "f"(b), "f"(c), "f"(d) : "memory");
}

// ------------------- kernel 1: transpose weights to k-major (+ zero stats) -------------------
__global__ void prepack(const float* __restrict__ W1, const float* __restrict__ W2,
                        const float* __restrict__ W3, const float* __restrict__ W4,
                        const float* __restrict__ We, const float* __restrict__ b1,
                        const float* __restrict__ b2, const float* __restrict__ b3,
                        const float* __restrict__ b4) {
    int t = blockIdx.x * blockDim.x + threadIdx.x;
    if (t < 4096) {
        int j = t >> 6, k = t & 63;
        int o = k * 256 + j;
        g_WtN[o]       = W1[t];
        g_WtN[o + 64]  = W2[t];
        g_WtN[o + 128] = W3[t];
        g_WtN[o + 192] = W4[t];
        g_WtE[k * 64 + j] = We[t];
    }
    if (t < 64) {
        g_bN[t] = b1[t]; g_bN[64 + t] = b2[t]; g_bN[128 + t] = b3[t]; g_bN[192 + t] = b4[t];
    }
    if (t < 128) { g_nstat[t] = 0.0f; g_estat[t] = 0.0f; }
}

// ------------------- kernel 2: node GEMMs (x1..x4 fused, f32x2) + zero sums -------------------
#define NODE_SMEM ((16384 + 32 * 68 + 256) * 4)
__global__ __launch_bounds__(256, 2) void node_gemm(const float* __restrict__ x) {
    extern __shared__ float sm[];
    float* WtS = sm;
    float* xs  = sm + 16384;
    float* bS  = sm + 16384 + 2176;
    int tid = threadIdx.x;
    for (int i = tid; i < 16384; i += 256) WtS[i] = g_WtN[i];
    bS[tid] = g_bN[tid];
    __syncthreads();

    int c32 = tid & 31, rg = tid >> 5;
    int j0 = c32 * 4, j1 = 128 + c32 * 4;
    u64 biasv[4] = { pack2(bS[j0], bS[j0 + 1]), pack2(bS[j0 + 2], bS[j0 + 3]),
                     pack2(bS[j1], bS[j1 + 1]), pack2(bS[j1 + 2], bS[j1 + 3]) };

    const float4 z4 = make_float4(0.f, 0.f, 0.f, 0.f);
    const int NT = N_NODES / 32;
    for (int tile = blockIdx.x; tile < NT; tile += gridDim.x) {
        int base = tile * 32;
        const float4* gp = (const float4*)(x + (size_t)base * DD);
        for (int f = tid; f < 512; f += 256) {
            float4 v = gp[f];
            int row = f >> 4, c4 = f & 15;
            *(float4*)&xs[row * 68 + c4 * 4] = v;
            ((float4*)(g_sums + (size_t)base * 64))[f] = z4;
        }
        if (tid < 32) g_cnt[base + tid] = 0.0f;
        __syncthreads();

        u64 acc[4][4];
        #pragma unroll
        for (int rr = 0; rr < 4; rr++) {
            acc[rr][0] = biasv[0]; acc[rr][1] = biasv[1];
            acc[rr][2] = biasv[2]; acc[rr][3] = biasv[3];
        }
        #pragma unroll
        for (int k0 = 0; k0 < 64; k0 += 4) {
            float xr[4][4];
            #pragma unroll
            for (int rr = 0; rr < 4; rr++) {
                float4 a = *(const float4*)&xs[(rg + 8 * rr) * 68 + k0];
                xr[rr][0] = a.x; xr[rr][1] = a.y; xr[rr][2] = a.z; xr[rr][3] = a.w;
            }
            #pragma unroll
            for (int kk = 0; kk < 4; kk++) {
                int k = k0 + kk;
                ulonglong2 wa = *(const ulonglong2*)&WtS[k * 256 + j0];
                ulonglong2 wb = *(const ulonglong2*)&WtS[k * 256 + j1];
                #pragma unroll
                for (int rr = 0; rr < 4; rr++) {
                    u64 av = bcast2(xr[rr][kk]);
                    fma2(acc[rr][0], av, wa.x); fma2(acc[rr][1], av, wa.y);
                    fma2(acc[rr][2], av, wb.x); fma2(acc[rr][3], av, wb.y);
                }
            }
        }
        #pragma unroll
        for (int rr = 0; rr < 4; rr++) {
            int n = base + rg + 8 * rr;
            float2 a0 = unpack2(acc[rr][0]), a1 = unpack2(acc[rr][1]);
            float2 a2 = unpack2(acc[rr][2]), a3 = unpack2(acc[rr][3]);
            float4 vA = make_float4(a0.x, a0.y, a1.x, a1.y);
            float4 vB = make_float4(a2.x, a2.y, a3.x, a3.y);
            float* pA = (c32 < 16) ? &g_x1[(size_t)n * 64 + j0]
                                   : &g_x24[(size_t)n * 128 + (j0 - 64)];
            float* pB = (c32 < 16) ? &g_x3[(size_t)n * 64 + (j1 - 128)]
                                   : &g_x24[(size_t)n * 128 + 64 + (j1 - 192)];
            *(float4*)pA = vA;
            *(float4*)pB = vB;
        }
        __syncthreads();
    }
}

// ------------------- kernel 3: edge pass 1 (cp.async pipelined, 1-deep gathers; R3 structure) -------------------
#define W0S_OFF   4096
#define W0S_STRIDE 8704
#define BES_OFF   (4096 + 2 * 8704)
#define IDX_OFF   (BES_OFF + 64)
#define EDGE_SMEM ((IDX_OFF + 512) * 4)
#define ETILES (N_EDGES / 128)

__device__ __forceinline__ void prefetch_tile(float* w0buf, int* sbuf, int* dbuf,
                                              const float* __restrict__ ea,
                                              const int* __restrict__ srcp,
                                              const int* __restrict__ dstp,
                                              int base, int tid, u64 pol) {
    if (tid < 32) {
        cpa16(sm2u(sbuf + tid * 4), srcp + base + tid * 4);
    } else if (tid < 64) {
        int i = tid - 32;
        cpa16(sm2u(dbuf + i * 4), dstp + base + i * 4);
    }
    const float4* gp = (const float4*)(ea + (size_t)base * DD);
    #pragma unroll
    for (int u = 0; u < 8; u++) {
        int f = tid + u * 256;                 // 2048 float4s = full 128x64 tile
        int row = f >> 4, c4 = f & 15;
        cpa16_pol(sm2u(w0buf + row * 68 + c4 * 4), gp + f, pol);
    }
}

__global__ __launch_bounds__(256, 2)
void edge_pass1(const float* __restrict__ ea, const int* __restrict__ srcp,
                const int* __restrict__ dstp, const float* __restrict__ be) {
    extern __shared__ float sm[];
    float* WtS = sm;
    float* beS = sm + BES_OFF;
    int* sS = (int*)(sm + IDX_OFF);
    int* dS = sS + 256;

    int tid = threadIdx.x;
    u64 pol = mkpolicy_evict_first();
    for (int i = tid; i < 4096; i += 256) WtS[i] = g_WtE[i];
    if (tid < 64) beS[tid] = be[tid];

    prefetch_tile(sm + W0S_OFF, sS, dS, ea, srcp, dstp, blockIdx.x * 128, tid, pol);
    cpa_commit();
    __syncthreads();

    int c8 = tid & 7, rq = tid >> 3;
    int j0 = c8 * 4, j1 = 32 + c8 * 4;
    u64 biasv[4] = { pack2(beS[j0], beS[j0 + 1]), pack2(beS[j0 + 2], beS[j0 + 3]),
                     pack2(beS[j1], beS[j1 + 1]), pack2(beS[j1 + 2], beS[j1 + 3]) };

    float ssum[8], sssq[8];
    #pragma unroll
    for (int i = 0; i < 8; i++) { ssum[i] = 0.0f; sssq[i] = 0.0f; }

    int buf = 0;
    for (int tile = blockIdx.x; tile < ETILES; tile += gridDim.x) {
        cpa_wait0();
        __syncthreads();
        float* w0c = sm + W0S_OFF + buf * W0S_STRIDE;
        int* sC = sS + buf * 128;
        int* dC = dS + buf * 128;
        int base = tile * 128;

        // ---- early gather for row rr=0 (hidden under GEMV) ----
        int s_cur = sC[rq], d_cur = dC[rq];
        const float* x3p = g_x3 + (size_t)s_cur * 64;
        const float* x24p = g_x24 + (size_t)d_cur * 128;
        float4 p0 = *(const float4*)(x3p + j0);
        float4 p1 = *(const float4*)(x3p + j1);
        float4 p2 = *(const float4*)(x24p + j0);
        float4 p3 = *(const float4*)(x24p + j1);
        float4 p4 = *(const float4*)(x24p + 64 + j0);
        float4 p5 = *(const float4*)(x24p + 64 + j1);

        // ---- issue next tile's prefetch (overlaps GEMV) ----
        int ntile = tile + gridDim.x;
        if (ntile < ETILES)
            prefetch_tile(sm + W0S_OFF + (buf ^ 1) * W0S_STRIDE,
                          sS + (buf ^ 1) * 128, dS + (buf ^ 1) * 128,
                          ea, srcp, dstp, ntile * 128, tid, pol);
        cpa_commit();

        // ---- GEMV: w1 = w0 @ We^T + be ----
        u64 acc[4][4];
        #pragma unroll
        for (int rr = 0; rr < 4; rr++) {
            acc[rr][0] = biasv[0]; acc[rr][1] = biasv[1];
            acc[rr][2] = biasv[2]; acc[rr][3] = biasv[3];
        }
        #pragma unroll
        for (int k0 = 0; k0 < 64; k0 += 4) {
            float w0r[4][4];
            #pragma unroll
            for (int rr = 0; rr < 4; rr++) {
                float4 a = *(const float4*)&w0c[(rq + 32 * rr) * 68 + k0];
                w0r[rr][0] = a.x; w0r[rr][1] = a.y; w0r[rr][2] = a.z; w0r[rr][3] = a.w;
            }
            #pragma unroll
            for (int kk = 0; kk < 4; kk++) {
                int k = k0 + kk;
                ulonglong2 wa = *(const ulonglong2*)&WtS[k * 64 + j0];
                ulonglong2 wb = *(const ulonglong2*)&WtS[k * 64 + j1];
                #pragma unroll
                for (int rr = 0; rr < 4; rr++) {
                    u64 av = bcast2(w0r[rr][kk]);
                    fma2(acc[rr][0], av, wa.x); fma2(acc[rr][1], av, wa.y);
                    fma2(acc[rr][2], av, wb.x); fma2(acc[rr][3], av, wb.y);
                }
            }
        }

        // ---- combine: software-pipelined over the 4 rows (1-deep) ----
        #pragma unroll
        for (int rr = 0; rr < 4; rr++) {
            int row = rq + 32 * rr;
            float4 x3a = p0, x3b = p1, x2a = p2, x2b = p3, x4a = p4, x4b = p5;
            int s_use = s_cur;
            if (rr < 3) {
                int nrow = row + 32;
                s_cur = sC[nrow]; d_cur = dC[nrow];
                const float* nx3 = g_x3 + (size_t)s_cur * 64;
                const float* nx24 = g_x24 + (size_t)d_cur * 128;
                p0 = *(const float4*)(nx3 + j0);
                p1 = *(const float4*)(nx3 + j1);
                p2 = *(const float4*)(nx24 + j0);
                p3 = *(const float4*)(nx24 + j1);
                p4 = *(const float4*)(nx24 + 64 + j0);
                p5 = *(const float4*)(nx24 + 64 + j1);
            }

            float2 w1_0 = unpack2(acc[rr][0]), w1_1 = unpack2(acc[rr][1]);
            float2 w1_2 = unpack2(acc[rr][2]), w1_3 = unpack2(acc[rr][3]);
            float tv[8];
            tv[0] = w1_0.x + x3a.x + x4a.x;
            tv[1] = w1_0.y + x3a.y + x4a.y;
            tv[2] = w1_1.x + x3a.z + x4a.z;
            tv[3] = w1_1.y + x3a.w + x4a.w;
            tv[4] = w1_2.x + x3b.x + x4b.x;
            tv[5] = w1_2.y + x3b.y + x4b.y;
            tv[6] = w1_3.x + x3b.z + x4b.z;
            tv[7] = w1_3.y + x3b.w + x4b.w;
            size_t eb = (size_t)(base + row) * 64;
            __stcs((float4*)&g_t[eb + j0], make_float4(tv[0], tv[1], tv[2], tv[3]));
            __stcs((float4*)&g_t[eb + j1], make_float4(tv[4], tv[5], tv[6], tv[7]));
            #pragma unroll
            for (int i = 0; i < 8; i++) {
                ssum[i] += tv[i];
                sssq[i] = fmaf(tv[i], tv[i], sssq[i]);
            }
            float4 wva = *(const float4*)&w0c[row * 68 + j0];
            float4 wvb = *(const float4*)&w0c[row * 68 + j1];
            float* sp = g_sums + (size_t)s_use * 64;
            red4(sp + j0, sigmoidf(wva.x) * x2a.x, sigmoidf(wva.y) * x2a.y,
                          sigmoidf(wva.z) * x2a.z, sigmoidf(wva.w) * x2a.w);
            red4(sp + j1, sigmoidf(wvb.x) * x2b.x, sigmoidf(wvb.y) * x2b.y,
                          sigmoidf(wvb.z) * x2b.z, sigmoidf(wvb.w) * x2b.w);
            if (c8 == 0) atomicAdd(&g_cnt[s_use], 1.0f);
        }
        buf ^= 1;
    }

    // flush BN stats
    #pragma unroll
    for (int i = 0; i < 8; i++) {
        ssum[i] += __shfl_xor_sync(0xffffffffu, ssum[i], 8);
        ssum[i] += __shfl_xor_sync(0xffffffffu, ssum[i], 16);
        sssq[i] += __shfl_xor_sync(0xffffffffu, sssq[i], 8);
        sssq[i] += __shfl_xor_sync(0xffffffffu, sssq[i], 16);
    }
    if ((tid & 24) == 0) {
        #pragma unroll
        for (int i = 0; i < 8; i++) {
            int col = (i < 4) ? (j0 + i) : (j1 + i - 4);
            atomicAdd(&g_estat[col], ssum[i]);
            atomicAdd(&g_estat[64 + col], sssq[i]);
        }
    }
}

// ------------------- kernel 4: node pre-BN + stats (wide grid, high MLP) -------------------
#define NS_BLOCKS 2048
__global__ void node_stats() {
    int t = blockIdx.x * blockDim.x + threadIdx.x;
    int c = (t & 15) * 4;
    int stride = (NS_BLOCKS * 256) >> 4;   // rows per sweep
    float s0 = 0, s1 = 0, s2 = 0, s3 = 0, q0 = 0, q1 = 0, q2 = 0, q3 = 0;
    for (int n = t >> 4; n < N_NODES; n += stride) {
        size_t off = (size_t)n * 64 + c;
        float4 a = __ldcg((const float4*)&g_x1[off]);
        float4 g = __ldcg((const float4*)&g_sums[off]);
        float inv = 1.0f / fmaxf(__ldcg(&g_cnt[n]), 1.0f);
        float4 y;
        y.x = fmaf(g.x, inv, a.x);
        y.y = fmaf(g.y, inv, a.y);
        y.z = fmaf(g.z, inv, a.z);
        y.w = fmaf(g.w, inv, a.w);
        *(float4*)&g_y[off] = y;
        s0 += y.x; q0 = fmaf(y.x, y.x, q0);
        s1 += y.y; q1 = fmaf(y.y, y.y, q1);
        s2 += y.z; q2 = fmaf(y.z, y.z, q2);
        s3 += y.w; q3 = fmaf(y.w, y.w, q3);
    }
    s0 += __shfl_xor_sync(0xffffffffu, s0, 16);
    s1 += __shfl_xor_sync(0xffffffffu, s1, 16);
    s2 += __shfl_xor_sync(0xffffffffu, s2, 16);
    s3 += __shfl_xor_sync(0xffffffffu, s3, 16);
    q0 += __shfl_xor_sync(0xffffffffu, q0, 16);
    q1 += __shfl_xor_sync(0xffffffffu, q1, 16);
    q2 += __shfl_xor_sync(0xffffffffu, q2, 16);
    q3 += __shfl_xor_sync(0xffffffffu, q3, 16);
    if ((threadIdx.x & 16) == 0) {
        atomicAdd(&g_nstat[c + 0], s0);
        atomicAdd(&g_nstat[c + 1], s1);
        atomicAdd(&g_nstat[c + 2], s2);
        atomicAdd(&g_nstat[c + 3], s3);
        atomicAdd(&g_nstat[64 + c + 0], q0);
        atomicAdd(&g_nstat[64 + c + 1], q1);
        atomicAdd(&g_nstat[64 + c + 2], q2);
        atomicAdd(&g_nstat[64 + c + 3], q3);
    }
}

// ------------------- kernel 5: fused BN + SiLU + residual -------------------
#define APPLY_NODE_BLOCKS 512
#define APPLY_EDGE_BLOCKS 4096
__global__ void apply_fused(const float* __restrict__ x, const float* __restrict__ ea,
                            const float* __restrict__ vg, const float* __restrict__ vb,
                            const float* __restrict__ eg, const float* __restrict__ eb,
                            float* __restrict__ out) {
    bool isEdge = blockIdx.x >= APPLY_NODE_BLOCKS;
    int bid     = isEdge ? (blockIdx.x - APPLY_NODE_BLOCKS) : blockIdx.x;
    int nblocks = isEdge ? APPLY_EDGE_BLOCKS : APPLY_NODE_BLOCKS;
    int rows    = isEdge ? N_EDGES : N_NODES;
    float invRows = isEdge ? (1.0f / (float)N_EDGES) : (1.0f / (float)N_NODES);
    const float* ybuf  = isEdge ? g_t : g_y;
    const float* stat  = isEdge ? g_estat : g_nstat;
    const float* resid = isEdge ? ea : x;
    const float* gamma = isEdge ? eg : vg;
    const float* beta  = isEdge ? eb : vb;
    float* ob = isEdge ? (out + (size_t)N_NODES * DD) : out;

    int t = bid * blockDim.x + threadIdx.x;
    int c = (t & 15) * 4;
    float A[4], B[4];
    #pragma unroll
    for (int i = 0; i < 4; i++) {
        float m = stat[c + i] * invRows;
        float var = stat[64 + c + i] * invRows - m * m;
        float rs = rsqrtf(var + 1e-5f);
        float gs = gamma[c + i] * rs;
        A[i] = gs;
        B[i] = fmaf(-m, gs, beta[c + i]);
    }
    int stride = (nblocks * blockDim.x) >> 4;
    for (int r = t >> 4; r < rows; r += stride) {
        size_t off = (size_t)r * 64 + c;
        float4 y = __ldcs((const float4*)(ybuf + off));
        float4 xv = __ldcs((const float4*)(resid + off));
        float z0 = fmaf(y.x, A[0], B[0]);
        float z1 = fmaf(y.y, A[1], B[1]);
        float z2 = fmaf(y.z, A[2], B[2]);
        float z3 = fmaf(y.w, A[3], B[3]);
        float4 o;
        o.x = xv.x + z0 * sigmoidf(z0);
        o.y = xv.y + z1 * sigmoidf(z1);
        o.z = xv.z + z2 * sigmoidf(z2);
        o.w = xv.w + z3 * sigmoidf(z3);
        __stcs((float4*)(ob + off), o);
    }
}

// ------------------- launch -------------------
extern "C" void kernel_launch(void* const* d_in, const int* in_sizes, int n_in,
                              void* d_out, int out_size) {
    const float* x   = (const float*)d_in[0];
    const float* ea  = (const float*)d_in[1];
    const float* W1  = (const float*)d_in[2];
    const float* b1  = (const float*)d_in[3];
    const float* W2  = (const float*)d_in[4];
    const float* b2  = (const float*)d_in[5];
    const float* W3  = (const float*)d_in[6];
    const float* b3  = (const float*)d_in[7];
    const float* W4  = (const float*)d_in[8];
    const float* b4  = (const float*)d_in[9];
    const float* We  = (const float*)d_in[10];
    const float* be  = (const float*)d_in[11];
    const float* vg  = (const float*)d_in[12];
    const float* vb  = (const float*)d_in[13];
    const float* eg  = (const float*)d_in[14];
    const float* ebt = (const float*)d_in[15];
    const int*   ei  = (const int*)d_in[16];
    const int* srcp = ei;
    const int* dstp = ei + N_EDGES;
    float* out = (float*)d_out;

    cudaFuncSetAttribute(node_gemm, cudaFuncAttributeMaxDynamicSharedMemorySize, NODE_SMEM);
    cudaFuncSetAttribute(edge_pass1, cudaFuncAttributeMaxDynamicSharedMemorySize, EDGE_SMEM);

    prepack<<<16, 256>>>(W1, W2, W3, W4, We, b1, b2, b3, b4);
    node_gemm<<<296, 256, NODE_SMEM>>>(x);
    edge_pass1<<<296, 256, EDGE_SMEM>>>(ea, srcp, dstp, be);
    node_stats<<<NS_BLOCKS, 256>>>();
    apply_fused<<<APPLY_NODE_BLOCKS + APPLY_EDGE_BLOCKS, 256>>>(x, ea, vg, vb, eg, ebt, out);
}

// round 6
// speedup vs baseline: 1.4928x; 1.4928x over previous
#include <cuda_runtime.h>
#include <cstdint>

#define N_NODES 100000
#define N_EDGES 1600000
#define DD 64

typedef unsigned long long u64;

// ------------------- scratch (static device globals; no allocation) -------------------
__device__ float g_x1[(size_t)N_NODES * DD];        // x@W1^T+b1
__device__ float g_x3[(size_t)N_NODES * DD];        // x@W3^T+b3
__device__ float g_x24[(size_t)N_NODES * 2 * DD];   // per node: [x2 row | x4 row]
__device__ float g_y[(size_t)N_NODES * DD];         // x1 + aggregated (pre-BN node)
__device__ float g_sums[(size_t)N_NODES * DD];      // scatter-add accumulator
__device__ float g_cnt[N_NODES];                    // per-src edge counts
__device__ float g_t[(size_t)N_EDGES * DD];         // pre-BN edge tensor (409.6 MB)
__device__ float g_WtN[64 * 256];                   // k-major stacked [W1|W2|W3|W4]
__device__ float g_bN[256];
__device__ float g_WtE[64 * 64];                    // k-major We
__device__ float g_nstat[128];                      // node: sum[64], ssq[64]
__device__ float g_estat[128];                      // edge: sum[64], ssq[64]

// ------------------- helpers -------------------
__device__ __forceinline__ u64 pack2(float lo, float hi) {
    u64 r; unsigned a = __float_as_uint(lo), b = __float_as_uint(hi);
    asm("mov.b64 %0, {%1,%2};" : "=l"(r) : "r"(a), "r"(b));
    return r;
}
__device__ __forceinline__ u64 bcast2(float v) {
    u64 r; unsigned a = __float_as_uint(v);
    asm("mov.b64 %0, {%1,%1};" : "=l"(r) : "r"(a));
    return r;
}
__device__ __forceinline__ void fma2(u64& d, u64 a, u64 b) {
    asm("fma.rn.f32x2 %0, %1, %2, %0;" : "+l"(d) : "l"(a), "l"(b));
}
__device__ __forceinline__ float2 unpack2(u64 v) {
    unsigned lo, hi;
    asm("mov.b64 {%0,%1}, %2;" : "=r"(lo), "=r"(hi) : "l"(v));
    return make_float2(__uint_as_float(lo), __uint_as_float(hi));
}
__device__ __forceinline__ float sigmoidf(float x) { return 1.0f / (1.0f + __expf(-x)); }

__device__ __forceinline__ unsigned sm2u(const void* p) {
    return (unsigned)__cvta_generic_to_shared(p);
}
__device__ __forceinline__ u64 mkpolicy_evict_first() {
    u64 p;
    asm("createpolicy.fractional.L2::evict_first.b64 %0, 1.0;" : "=l"(p));
    return p;
}
__device__ __forceinline__ void cpa16(unsigned s, const void* g) {
    asm volatile("cp.async.cg.shared.global [%0], [%1], 16;" :: "r"(s), "l"(g));
}
__device__ __forceinline__ void cpa16_pol(unsigned s, const void* g, u64 pol) {
    asm volatile("cp.async.cg.shared.global.L2::cache_hint [%0], [%1], 16, %2;"
                 :: "r"(s), "l"(g), "l"(pol));
}
__device__ __forceinline__ void cpa_commit() {
    asm volatile("cp.async.commit_group;");
}
__device__ __forceinline__ void cpa_wait0() {
    asm volatile("cp.async.wait_group 0;");
}
__device__ __forceinline__ void red4(float* p, float a, float b, float c, float d) {
    asm volatile("red.global.add.v4.f32 [%0], {%1,%2,%3,%4};"
                 :: "l"(p), "f"(a), "f"(b), "f"(c), "f"(d) : "memory");
}

// ------------------- kernel 1: transpose weights to k-major (+ zero stats) -------------------
__global__ void prepack(const float* __restrict__ W1, const float* __restrict__ W2,
                        const float* __restrict__ W3, const float* __restrict__ W4,
                        const float* __restrict__ We, const float* __restrict__ b1,
                        const float* __restrict__ b2, const float* __restrict__ b3,
                        const float* __restrict__ b4) {
    int t = blockIdx.x * blockDim.x + threadIdx.x;
    if (t < 4096) {
        int j = t >> 6, k = t & 63;
        int o = k * 256 + j;
        g_WtN[o]       = W1[t];
        g_WtN[o + 64]  = W2[t];
        g_WtN[o + 128] = W3[t];
        g_WtN[o + 192] = W4[t];
        g_WtE[k * 64 + j] = We[t];
    }
    if (t < 64) {
        g_bN[t] = b1[t]; g_bN[64 + t] = b2[t]; g_bN[128 + t] = b3[t]; g_bN[192 + t] = b4[t];
    }
    if (t < 128) { g_nstat[t] = 0.0f; g_estat[t] = 0.0f; }
}

// ------------------- kernel 2: node GEMMs (x1..x4 fused, f32x2) + zero sums -------------------
#define NODE_SMEM ((16384 + 32 * 68 + 256) * 4)
__global__ __launch_bounds__(256, 2) void node_gemm(const float* __restrict__ x) {
    extern __shared__ float sm[];
    float* WtS = sm;
    float* xs  = sm + 16384;
    float* bS  = sm + 16384 + 2176;
    int tid = threadIdx.x;
    for (int i = tid; i < 16384; i += 256) WtS[i] = g_WtN[i];
    bS[tid] = g_bN[tid];
    __syncthreads();

    int c32 = tid & 31, rg = tid >> 5;
    int j0 = c32 * 4, j1 = 128 + c32 * 4;
    u64 biasv[4] = { pack2(bS[j0], bS[j0 + 1]), pack2(bS[j0 + 2], bS[j0 + 3]),
                     pack2(bS[j1], bS[j1 + 1]), pack2(bS[j1 + 2], bS[j1 + 3]) };

    const float4 z4 = make_float4(0.f, 0.f, 0.f, 0.f);
    const int NT = N_NODES / 32;
    for (int tile = blockIdx.x; tile < NT; tile += gridDim.x) {
        int base = tile * 32;
        const float4* gp = (const float4*)(x + (size_t)base * DD);
        for (int f = tid; f < 512; f += 256) {
            float4 v = gp[f];
            int row = f >> 4, c4 = f & 15;
            *(float4*)&xs[row * 68 + c4 * 4] = v;
            ((float4*)(g_sums + (size_t)base * 64))[f] = z4;
        }
        if (tid < 32) g_cnt[base + tid] = 0.0f;
        __syncthreads();

        u64 acc[4][4];
        #pragma unroll
        for (int rr = 0; rr < 4; rr++) {
            acc[rr][0] = biasv[0]; acc[rr][1] = biasv[1];
            acc[rr][2] = biasv[2]; acc[rr][3] = biasv[3];
        }
        #pragma unroll
        for (int k0 = 0; k0 < 64; k0 += 4) {
            float xr[4][4];
            #pragma unroll
            for (int rr = 0; rr < 4; rr++) {
                float4 a = *(const float4*)&xs[(rg + 8 * rr) * 68 + k0];
                xr[rr][0] = a.x; xr[rr][1] = a.y; xr[rr][2] = a.z; xr[rr][3] = a.w;
            }
            #pragma unroll
            for (int kk = 0; kk < 4; kk++) {
                int k = k0 + kk;
                ulonglong2 wa = *(const ulonglong2*)&WtS[k * 256 + j0];
                ulonglong2 wb = *(const ulonglong2*)&WtS[k * 256 + j1];
                #pragma unroll
                for (int rr = 0; rr < 4; rr++) {
                    u64 av = bcast2(xr[rr][kk]);
                    fma2(acc[rr][0], av, wa.x); fma2(acc[rr][1], av, wa.y);
                    fma2(acc[rr][2], av, wb.x); fma2(acc[rr][3], av, wb.y);
                }
            }
        }
        #pragma unroll
        for (int rr = 0; rr < 4; rr++) {
            int n = base + rg + 8 * rr;
            float2 a0 = unpack2(acc[rr][0]), a1 = unpack2(acc[rr][1]);
            float2 a2 = unpack2(acc[rr][2]), a3 = unpack2(acc[rr][3]);
            float4 vA = make_float4(a0.x, a0.y, a1.x, a1.y);
            float4 vB = make_float4(a2.x, a2.y, a3.x, a3.y);
            float* pA = (c32 < 16) ? &g_x1[(size_t)n * 64 + j0]
                                   : &g_x24[(size_t)n * 128 + (j0 - 64)];
            float* pB = (c32 < 16) ? &g_x3[(size_t)n * 64 + (j1 - 128)]
                                   : &g_x24[(size_t)n * 128 + 64 + (j1 - 192)];
            *(float4*)pA = vA;
            *(float4*)pB = vB;
        }
        __syncthreads();
    }
}

// ------------------- kernel 3: edge pass 1 (cp.async pipelined, 1-deep gathers) -------------------
#define W0S_OFF   4096
#define W0S_STRIDE 8704
#define BES_OFF   (4096 + 2 * 8704)
#define IDX_OFF   (BES_OFF + 64)
#define EDGE_SMEM ((IDX_OFF + 512) * 4)
#define ETILES (N_EDGES / 128)

__device__ __forceinline__ void prefetch_tile(float* w0buf, int* sbuf, int* dbuf,
                                              const float* __restrict__ ea,
                                              const int* __restrict__ srcp,
                                              const int* __restrict__ dstp,
                                              int base, int tid, u64 pol) {
    if (tid < 32) {
        cpa16(sm2u(sbuf + tid * 4), srcp + base + tid * 4);
    } else if (tid < 64) {
        int i = tid - 32;
        cpa16(sm2u(dbuf + i * 4), dstp + base + i * 4);
    }
    const float4* gp = (const float4*)(ea + (size_t)base * DD);
    #pragma unroll
    for (int u = 0; u < 8; u++) {
        int f = tid + u * 256;                 // 2048 float4s = full 128x64 tile
        int row = f >> 4, c4 = f & 15;
        cpa16_pol(sm2u(w0buf + row * 68 + c4 * 4), gp + f, pol);
    }
}

__global__ __launch_bounds__(256, 2)
void edge_pass1(const float* __restrict__ ea, const int* __restrict__ srcp,
                const int* __restrict__ dstp, const float* __restrict__ be) {
    extern __shared__ float sm[];
    float* WtS = sm;
    float* beS = sm + BES_OFF;
    int* sS = (int*)(sm + IDX_OFF);
    int* dS = sS + 256;

    int tid = threadIdx.x;
    u64 pol = mkpolicy_evict_first();
    for (int i = tid; i < 4096; i += 256) WtS[i] = g_WtE[i];
    if (tid < 64) beS[tid] = be[tid];

    prefetch_tile(sm + W0S_OFF, sS, dS, ea, srcp, dstp, blockIdx.x * 128, tid, pol);
    cpa_commit();
    __syncthreads();

    int c8 = tid & 7, rq = tid >> 3;
    int j0 = c8 * 4, j1 = 32 + c8 * 4;
    u64 biasv[4] = { pack2(beS[j0], beS[j0 + 1]), pack2(beS[j0 + 2], beS[j0 + 3]),
                     pack2(beS[j1], beS[j1 + 1]), pack2(beS[j1 + 2], beS[j1 + 3]) };

    float ssum[8], sssq[8];
    #pragma unroll
    for (int i = 0; i < 8; i++) { ssum[i] = 0.0f; sssq[i] = 0.0f; }

    int buf = 0;
    for (int tile = blockIdx.x; tile < ETILES; tile += gridDim.x) {
        cpa_wait0();
        __syncthreads();
        float* w0c = sm + W0S_OFF + buf * W0S_STRIDE;
        int* sC = sS + buf * 128;
        int* dC = dS + buf * 128;
        int base = tile * 128;

        // ---- early gather for row rr=0 (hidden under GEMV) ----
        int s_cur = sC[rq], d_cur = dC[rq];
        const float* x3p = g_x3 + (size_t)s_cur * 64;
        const float* x24p = g_x24 + (size_t)d_cur * 128;
        float4 p0 = *(const float4*)(x3p + j0);
        float4 p1 = *(const float4*)(x3p + j1);
        float4 p2 = *(const float4*)(x24p + j0);
        float4 p3 = *(const float4*)(x24p + j1);
        float4 p4 = *(const float4*)(x24p + 64 + j0);
        float4 p5 = *(const float4*)(x24p + 64 + j1);

        // ---- issue next tile's prefetch (overlaps GEMV) ----
        int ntile = tile + gridDim.x;
        if (ntile < ETILES)
            prefetch_tile(sm + W0S_OFF + (buf ^ 1) * W0S_STRIDE,
                          sS + (buf ^ 1) * 128, dS + (buf ^ 1) * 128,
                          ea, srcp, dstp, ntile * 128, tid, pol);
        cpa_commit();

        // ---- GEMV: w1 = w0 @ We^T + be ----
        u64 acc[4][4];
        #pragma unroll
        for (int rr = 0; rr < 4; rr++) {
            acc[rr][0] = biasv[0]; acc[rr][1] = biasv[1];
            acc[rr][2] = biasv[2]; acc[rr][3] = biasv[3];
        }
        #pragma unroll
        for (int k0 = 0; k0 < 64; k0 += 4) {
            float w0r[4][4];
            #pragma unroll
            for (int rr = 0; rr < 4; rr++) {
                float4 a = *(const float4*)&w0c[(rq + 32 * rr) * 68 + k0];
                w0r[rr][0] = a.x; w0r[rr][1] = a.y; w0r[rr][2] = a.z; w0r[rr][3] = a.w;
            }
            #pragma unroll
            for (int kk = 0; kk < 4; kk++) {
                int k = k0 + kk;
                ulonglong2 wa = *(const ulonglong2*)&WtS[k * 64 + j0];
                ulonglong2 wb = *(const ulonglong2*)&WtS[k * 64 + j1];
                #pragma unroll
                for (int rr = 0; rr < 4; rr++) {
                    u64 av = bcast2(w0r[rr][kk]);
                    fma2(acc[rr][0], av, wa.x); fma2(acc[rr][1], av, wa.y);
                    fma2(acc[rr][2], av, wb.x); fma2(acc[rr][3], av, wb.y);
                }
            }
        }

        // ---- combine: software-pipelined over the 4 rows (1-deep) ----
        #pragma unroll
        for (int rr = 0; rr < 4; rr++) {
            int row = rq + 32 * rr;
            float4 x3a = p0, x3b = p1, x2a = p2, x2b = p3, x4a = p4, x4b = p5;
            int s_use = s_cur;
            if (rr < 3) {
                int nrow = row + 32;
                s_cur = sC[nrow]; d_cur = dC[nrow];
                const float* nx3 = g_x3 + (size_t)s_cur * 64;
                const float* nx24 = g_x24 + (size_t)d_cur * 128;
                p0 = *(const float4*)(nx3 + j0);
                p1 = *(const float4*)(nx3 + j1);
                p2 = *(const float4*)(nx24 + j0);
                p3 = *(const float4*)(nx24 + j1);
                p4 = *(const float4*)(nx24 + 64 + j0);
                p5 = *(const float4*)(nx24 + 64 + j1);
            }

            float2 w1_0 = unpack2(acc[rr][0]), w1_1 = unpack2(acc[rr][1]);
            float2 w1_2 = unpack2(acc[rr][2]), w1_3 = unpack2(acc[rr][3]);
            float tv[8];
            tv[0] = w1_0.x + x3a.x + x4a.x;
            tv[1] = w1_0.y + x3a.y + x4a.y;
            tv[2] = w1_1.x + x3a.z + x4a.z;
            tv[3] = w1_1.y + x3a.w + x4a.w;
            tv[4] = w1_2.x + x3b.x + x4b.x;
            tv[5] = w1_2.y + x3b.y + x4b.y;
            tv[6] = w1_3.x + x3b.z + x4b.z;
            tv[7] = w1_3.y + x3b.w + x4b.w;
            size_t eb = (size_t)(base + row) * 64;
            __stcs((float4*)&g_t[eb + j0], make_float4(tv[0], tv[1], tv[2], tv[3]));
            __stcs((float4*)&g_t[eb + j1], make_float4(tv[4], tv[5], tv[6], tv[7]));
            #pragma unroll
            for (int i = 0; i < 8; i++) {
                ssum[i] += tv[i];
                sssq[i] = fmaf(tv[i], tv[i], sssq[i]);
            }
            float4 wva = *(const float4*)&w0c[row * 68 + j0];
            float4 wvb = *(const float4*)&w0c[row * 68 + j1];
            float* sp = g_sums + (size_t)s_use * 64;
            red4(sp + j0, sigmoidf(wva.x) * x2a.x, sigmoidf(wva.y) * x2a.y,
                          sigmoidf(wva.z) * x2a.z, sigmoidf(wva.w) * x2a.w);
            red4(sp + j1, sigmoidf(wvb.x) * x2b.x, sigmoidf(wvb.y) * x2b.y,
                          sigmoidf(wvb.z) * x2b.z, sigmoidf(wvb.w) * x2b.w);
            if (c8 == 0) atomicAdd(&g_cnt[s_use], 1.0f);
        }
        buf ^= 1;
    }

    // ---- flush BN stats: warp shfl -> smem block reduction -> 128 atomics/block ----
    #pragma unroll
    for (int i = 0; i < 8; i++) {
        ssum[i] += __shfl_xor_sync(0xffffffffu, ssum[i], 8);
        ssum[i] += __shfl_xor_sync(0xffffffffu, ssum[i], 16);
        sssq[i] += __shfl_xor_sync(0xffffffffu, sssq[i], 8);
        sssq[i] += __shfl_xor_sync(0xffffffffu, sssq[i], 16);
    }
    __syncthreads();               // main loop done in all warps; WtS region now reusable
    float* redb = sm;              // [8 warps][128 stats]
    int warp = tid >> 5, lane = tid & 31;
    if ((lane & 24) == 0) {        // lanes 0..7: hold the 8 col-values for this c8
        #pragma unroll
        for (int i = 0; i < 8; i++) {
            int col = (i < 4) ? (j0 + i) : (j1 + i - 4);
            redb[warp * 128 + col] = ssum[i];
            redb[warp * 128 + 64 + col] = sssq[i];
        }
    }
    __syncthreads();
    if (tid < 128) {
        float v = 0.0f;
        #pragma unroll
        for (int w = 0; w < 8; w++) v += redb[w * 128 + tid];
        atomicAdd(&g_estat[tid], v);
    }
}

// ------------------- kernel 4: node pre-BN + stats (smem-reduced atomics) -------------------
#define NS_BLOCKS 512
__global__ void node_stats() {
    __shared__ float redb[8 * 128];
    int tid = threadIdx.x;
    int t = blockIdx.x * 256 + tid;
    int c = (tid & 15) * 4;
    int stride = (NS_BLOCKS * 256) >> 4;
    float s0 = 0, s1 = 0, s2 = 0, s3 = 0, q0 = 0, q1 = 0, q2 = 0, q3 = 0;
    for (int n = t >> 4; n < N_NODES; n += stride) {
        size_t off = (size_t)n * 64 + c;
        float4 a = *(const float4*)&g_x1[off];
        float4 g = *(const float4*)&g_sums[off];
        float inv = 1.0f / fmaxf(g_cnt[n], 1.0f);
        float4 y;
        y.x = fmaf(g.x, inv, a.x);
        y.y = fmaf(g.y, inv, a.y);
        y.z = fmaf(g.z, inv, a.z);
        y.w = fmaf(g.w, inv, a.w);
        *(float4*)&g_y[off] = y;
        s0 += y.x; q0 = fmaf(y.x, y.x, q0);
        s1 += y.y; q1 = fmaf(y.y, y.y, q1);
        s2 += y.z; q2 = fmaf(y.z, y.z, q2);
        s3 += y.w; q3 = fmaf(y.w, y.w, q3);
    }
    s0 += __shfl_xor_sync(0xffffffffu, s0, 16);
    s1 += __shfl_xor_sync(0xffffffffu, s1, 16);
    s2 += __shfl_xor_sync(0xffffffffu, s2, 16);
    s3 += __shfl_xor_sync(0xffffffffu, s3, 16);
    q0 += __shfl_xor_sync(0xffffffffu, q0, 16);
    q1 += __shfl_xor_sync(0xffffffffu, q1, 16);
    q2 += __shfl_xor_sync(0xffffffffu, q2, 16);
    q3 += __shfl_xor_sync(0xffffffffu, q3, 16);
    int warp = tid >> 5, lane = tid & 31;
    if (lane < 16) {
        redb[warp * 128 + c + 0] = s0;
        redb[warp * 128 + c + 1] = s1;
        redb[warp * 128 + c + 2] = s2;
        redb[warp * 128 + c + 3] = s3;
        redb[warp * 128 + 64 + c + 0] = q0;
        redb[warp * 128 + 64 + c + 1] = q1;
        redb[warp * 128 + 64 + c + 2] = q2;
        redb[warp * 128 + 64 + c + 3] = q3;
    }
    __syncthreads();
    if (tid < 128) {
        float v = 0.0f;
        #pragma unroll
        for (int w = 0; w < 8; w++) v += redb[w * 128 + tid];
        atomicAdd(&g_nstat[tid], v);
    }
}

// ------------------- kernel 5: fused BN + SiLU + residual -------------------
#define APPLY_NODE_BLOCKS 512
#define APPLY_EDGE_BLOCKS 4096
__global__ void apply_fused(const float* __restrict__ x, const float* __restrict__ ea,
                            const float* __restrict__ vg, const float* __restrict__ vb,
                            const float* __restrict__ eg, const float* __restrict__ eb,
                            float* __restrict__ out) {
    bool isEdge = blockIdx.x >= APPLY_NODE_BLOCKS;
    int bid     = isEdge ? (blockIdx.x - APPLY_NODE_BLOCKS) : blockIdx.x;
    int nblocks = isEdge ? APPLY_EDGE_BLOCKS : APPLY_NODE_BLOCKS;
    int rows    = isEdge ? N_EDGES : N_NODES;
    float invRows = isEdge ? (1.0f / (float)N_EDGES) : (1.0f / (float)N_NODES);
    const float* ybuf  = isEdge ? g_t : g_y;
    const float* stat  = isEdge ? g_estat : g_nstat;
    const float* resid = isEdge ? ea : x;
    const float* gamma = isEdge ? eg : vg;
    const float* beta  = isEdge ? eb : vb;
    float* ob = isEdge ? (out + (size_t)N_NODES * DD) : out;

    int t = bid * blockDim.x + threadIdx.x;
    int c = (t & 15) * 4;
    float A[4], B[4];
    #pragma unroll
    for (int i = 0; i < 4; i++) {
        float m = stat[c + i] * invRows;
        float var = stat[64 + c + i] * invRows - m * m;
        float rs = rsqrtf(var + 1e-5f);
        float gs = gamma[c + i] * rs;
        A[i] = gs;
        B[i] = fmaf(-m, gs, beta[c + i]);
    }
    int stride = (nblocks * blockDim.x) >> 4;
    for (int r = t >> 4; r < rows; r += stride) {
        size_t off = (size_t)r * 64 + c;
        float4 y = __ldcs((const float4*)(ybuf + off));
        float4 xv = __ldcs((const float4*)(resid + off));
        float z0 = fmaf(y.x, A[0], B[0]);
        float z1 = fmaf(y.y, A[1], B[1]);
        float z2 = fmaf(y.z, A[2], B[2]);
        float z3 = fmaf(y.w, A[3], B[3]);
        float4 o;
        o.x = xv.x + z0 * sigmoidf(z0);
        o.y = xv.y + z1 * sigmoidf(z1);
        o.z = xv.z + z2 * sigmoidf(z2);
        o.w = xv.w + z3 * sigmoidf(z3);
        __stcs((float4*)(ob + off), o);
    }
}

// ------------------- launch -------------------
extern "C" void kernel_launch(void* const* d_in, const int* in_sizes, int n_in,
                              void* d_out, int out_size) {
    const float* x   = (const float*)d_in[0];
    const float* ea  = (const float*)d_in[1];
    const float* W1  = (const float*)d_in[2];
    const float* b1  = (const float*)d_in[3];
    const float* W2  = (const float*)d_in[4];
    const float* b2  = (const float*)d_in[5];
    const float* W3  = (const float*)d_in[6];
    const float* b3  = (const float*)d_in[7];
    const float* W4  = (const float*)d_in[8];
    const float* b4  = (const float*)d_in[9];
    const float* We  = (const float*)d_in[10];
    const float* be  = (const float*)d_in[11];
    const float* vg  = (const float*)d_in[12];
    const float* vb  = (const float*)d_in[13];
    const float* eg  = (const float*)d_in[14];
    const float* ebt = (const float*)d_in[15];
    const int*   ei  = (const int*)d_in[16];
    const int* srcp = ei;
    const int* dstp = ei + N_EDGES;
    float* out = (float*)d_out;

    cudaFuncSetAttribute(node_gemm, cudaFuncAttributeMaxDynamicSharedMemorySize, NODE_SMEM);
    cudaFuncSetAttribute(edge_pass1, cudaFuncAttributeMaxDynamicSharedMemorySize, EDGE_SMEM);

    prepack<<<16, 256>>>(W1, W2, W3, W4, We, b1, b2, b3, b4);
    node_gemm<<<296, 256, NODE_SMEM>>>(x);
    edge_pass1<<<296, 256, EDGE_SMEM>>>(ea, srcp, dstp, be);
    node_stats<<<NS_BLOCKS, 256>>>();
    apply_fused<<<APPLY_NODE_BLOCKS + APPLY_EDGE_BLOCKS, 256>>>(x, ea, vg, vb, eg, ebt, out);
}

// round 7
// speedup vs baseline: 1.5178x; 1.0168x over previous
#include <cuda_runtime.h>
#include <cuda_fp16.h>
#include <cstdint>

#define N_NODES 100000
#define N_EDGES 1600000
#define DD 64

typedef unsigned long long u64;

// ------------------- scratch (static device globals; no allocation) -------------------
__device__ float g_x1[(size_t)N_NODES * DD];        // x@W1^T+b1
__device__ float g_x3[(size_t)N_NODES * DD];        // x@W3^T+b3
__device__ float g_x24[(size_t)N_NODES * 2 * DD];   // per node: [x2 row | x4 row]
__device__ float g_y[(size_t)N_NODES * DD];         // x1 + aggregated (pre-BN node)
__device__ float g_sums[(size_t)N_NODES * DD];      // scatter-add accumulator
__device__ float g_cnt[N_NODES];                    // per-src edge counts
__device__ __half g_t[(size_t)N_EDGES * DD];        // pre-BN edge tensor (fp16, 204.8 MB)
__device__ float g_WtN[64 * 256];                   // k-major stacked [W1|W2|W3|W4]
__device__ float g_bN[256];
__device__ float g_WtE[64 * 64];                    // k-major We
__device__ float g_nstat[128];                      // node: sum[64], ssq[64]
__device__ float g_estat[128];                      // edge: sum[64], ssq[64]

// ------------------- helpers -------------------
__device__ __forceinline__ u64 pack2(float lo, float hi) {
    u64 r; unsigned a = __float_as_uint(lo), b = __float_as_uint(hi);
    asm("mov.b64 %0, {%1,%2};" : "=l"(r) : "r"(a), "r"(b));
    return r;
}
__device__ __forceinline__ u64 bcast2(float v) {
    u64 r; unsigned a = __float_as_uint(v);
    asm("mov.b64 %0, {%1,%1};" : "=l"(r) : "r"(a));
    return r;
}
__device__ __forceinline__ void fma2(u64& d, u64 a, u64 b) {
    asm("fma.rn.f32x2 %0, %1, %2, %0;" : "+l"(d) : "l"(a), "l"(b));
}
__device__ __forceinline__ float2 unpack2(u64 v) {
    unsigned lo, hi;
    asm("mov.b64 {%0,%1}, %2;" : "=r"(lo), "=r"(hi) : "l"(v));
    return make_float2(__uint_as_float(lo), __uint_as_float(hi));
}
__device__ __forceinline__ float sigmoidf(float x) { return 1.0f / (1.0f + __expf(-x)); }

__device__ __forceinline__ unsigned sm2u(const void* p) {
    return (unsigned)__cvta_generic_to_shared(p);
}
__device__ __forceinline__ u64 mkpolicy_evict_first() {
    u64 p;
    asm("createpolicy.fractional.L2::evict_first.b64 %0, 1.0;" : "=l"(p));
    return p;
}
__device__ __forceinline__ void cpa16(unsigned s, const void* g) {
    asm volatile("cp.async.cg.shared.global [%0], [%1], 16;" :: "r"(s), "l"(g));
}
__device__ __forceinline__ void cpa16_pol(unsigned s, const void* g, u64 pol) {
    asm volatile("cp.async.cg.shared.global.L2::cache_hint [%0], [%1], 16, %2;"
                 :: "r"(s), "l"(g), "l"(pol));
}
__device__ __forceinline__ void cpa_commit() {
    asm volatile("cp.async.commit_group;");
}
__device__ __forceinline__ void cpa_wait0() {
    asm volatile("cp.async.wait_group 0;");
}
__device__ __forceinline__ void red4(float* p, float a, float b, float c, float d) {
    asm volatile("red.global.add.v4.f32 [%0], {%1,%2,%3,%4};"
                 :: "l"(p), "f"(a), "f"(b), "f"(c), "f"(d) : "memory");
}
__device__ __forceinline__ void st8_cs(__half* p, unsigned a, unsigned b) {
    asm volatile("st.global.cs.v2.b32 [%0], {%1,%2};" :: "l"(p), "r"(a), "r"(b) : "memory");
}

// ------------------- kernel 1: transpose weights to k-major (+ zero stats) -------------------
__global__ void prepack(const float* __restrict__ W1, const float* __restrict__ W2,
                        const float* __restrict__ W3, const float* __restrict__ W4,
                        const float* __restrict__ We, const float* __restrict__ b1,
                        const float* __restrict__ b2, const float* __restrict__ b3,
                        const float* __restrict__ b4) {
    int t = blockIdx.x * blockDim.x + threadIdx.x;
    if (t < 4096) {
        int j = t >> 6, k = t & 63;
        int o = k * 256 + j;
        g_WtN[o]       = W1[t];
        g_WtN[o + 64]  = W2[t];
        g_WtN[o + 128] = W3[t];
        g_WtN[o + 192] = W4[t];
        g_WtE[k * 64 + j] = We[t];
    }
    if (t < 64) {
        g_bN[t] = b1[t]; g_bN[64 + t] = b2[t]; g_bN[128 + t] = b3[t]; g_bN[192 + t] = b4[t];
    }
    if (t < 128) { g_nstat[t] = 0.0f; g_estat[t] = 0.0f; }
}

// ------------------- kernel 2: node GEMMs (x1..x4 fused, f32x2) + zero sums -------------------
#define NODE_SMEM ((16384 + 32 * 68 + 256) * 4)
__global__ __launch_bounds__(256, 2) void node_gemm(const float* __restrict__ x) {
    extern __shared__ float sm[];
    float* WtS = sm;
    float* xs  = sm + 16384;
    float* bS  = sm + 16384 + 2176;
    int tid = threadIdx.x;
    for (int i = tid; i < 16384; i += 256) WtS[i] = g_WtN[i];
    bS[tid] = g_bN[tid];
    __syncthreads();

    int c32 = tid & 31, rg = tid >> 5;
    int j0 = c32 * 4, j1 = 128 + c32 * 4;
    u64 biasv[4] = { pack2(bS[j0], bS[j0 + 1]), pack2(bS[j0 + 2], bS[j0 + 3]),
                     pack2(bS[j1], bS[j1 + 1]), pack2(bS[j1 + 2], bS[j1 + 3]) };

    const float4 z4 = make_float4(0.f, 0.f, 0.f, 0.f);
    const int NT = N_NODES / 32;
    for (int tile = blockIdx.x; tile < NT; tile += gridDim.x) {
        int base = tile * 32;
        const float4* gp = (const float4*)(x + (size_t)base * DD);
        for (int f = tid; f < 512; f += 256) {
            float4 v = gp[f];
            int row = f >> 4, c4 = f & 15;
            *(float4*)&xs[row * 68 + c4 * 4] = v;
            ((float4*)(g_sums + (size_t)base * 64))[f] = z4;
        }
        if (tid < 32) g_cnt[base + tid] = 0.0f;
        __syncthreads();

        u64 acc[4][4];
        #pragma unroll
        for (int rr = 0; rr < 4; rr++) {
            acc[rr][0] = biasv[0]; acc[rr][1] = biasv[1];
            acc[rr][2] = biasv[2]; acc[rr][3] = biasv[3];
        }
        #pragma unroll
        for (int k0 = 0; k0 < 64; k0 += 4) {
            float xr[4][4];
            #pragma unroll
            for (int rr = 0; rr < 4; rr++) {
                float4 a = *(const float4*)&xs[(rg + 8 * rr) * 68 + k0];
                xr[rr][0] = a.x; xr[rr][1] = a.y; xr[rr][2] = a.z; xr[rr][3] = a.w;
            }
            #pragma unroll
            for (int kk = 0; kk < 4; kk++) {
                int k = k0 + kk;
                ulonglong2 wa = *(const ulonglong2*)&WtS[k * 256 + j0];
                ulonglong2 wb = *(const ulonglong2*)&WtS[k * 256 + j1];
                #pragma unroll
                for (int rr = 0; rr < 4; rr++) {
                    u64 av = bcast2(xr[rr][kk]);
                    fma2(acc[rr][0], av, wa.x); fma2(acc[rr][1], av, wa.y);
                    fma2(acc[rr][2], av, wb.x); fma2(acc[rr][3], av, wb.y);
                }
            }
        }
        #pragma unroll
        for (int rr = 0; rr < 4; rr++) {
            int n = base + rg + 8 * rr;
            float2 a0 = unpack2(acc[rr][0]), a1 = unpack2(acc[rr][1]);
            float2 a2 = unpack2(acc[rr][2]), a3 = unpack2(acc[rr][3]);
            float4 vA = make_float4(a0.x, a0.y, a1.x, a1.y);
            float4 vB = make_float4(a2.x, a2.y, a3.x, a3.y);
            float* pA = (c32 < 16) ? &g_x1[(size_t)n * 64 + j0]
                                   : &g_x24[(size_t)n * 128 + (j0 - 64)];
            float* pB = (c32 < 16) ? &g_x3[(size_t)n * 64 + (j1 - 128)]
                                   : &g_x24[(size_t)n * 128 + 64 + (j1 - 192)];
            *(float4*)pA = vA;
            *(float4*)pB = vB;
        }
        __syncthreads();
    }
}

// ------------------- kernel 3: edge pass 1 (cp.async pipelined, 1-deep gathers) -------------------
#define W0S_OFF   4096
#define W0S_STRIDE 8704
#define BES_OFF   (4096 + 2 * 8704)
#define IDX_OFF   (BES_OFF + 64)
#define EDGE_SMEM ((IDX_OFF + 512) * 4)
#define ETILES (N_EDGES / 128)

__device__ __forceinline__ void prefetch_tile(float* w0buf, int* sbuf, int* dbuf,
                                              const float* __restrict__ ea,
                                              const int* __restrict__ srcp,
                                              const int* __restrict__ dstp,
                                              int base, int tid, u64 pol) {
    if (tid < 32) {
        cpa16(sm2u(sbuf + tid * 4), srcp + base + tid * 4);
    } else if (tid < 64) {
        int i = tid - 32;
        cpa16(sm2u(dbuf + i * 4), dstp + base + i * 4);
    }
    const float4* gp = (const float4*)(ea + (size_t)base * DD);
    #pragma unroll
    for (int u = 0; u < 8; u++) {
        int f = tid + u * 256;                 // 2048 float4s = full 128x64 tile
        int row = f >> 4, c4 = f & 15;
        cpa16_pol(sm2u(w0buf + row * 68 + c4 * 4), gp + f, pol);
    }
}

__global__ __launch_bounds__(256, 2)
void edge_pass1(const float* __restrict__ ea, const int* __restrict__ srcp,
                const int* __restrict__ dstp, const float* __restrict__ be) {
    extern __shared__ float sm[];
    float* WtS = sm;
    float* beS = sm + BES_OFF;
    int* sS = (int*)(sm + IDX_OFF);
    int* dS = sS + 256;

    int tid = threadIdx.x;
    u64 pol = mkpolicy_evict_first();
    for (int i = tid; i < 4096; i += 256) WtS[i] = g_WtE[i];
    if (tid < 64) beS[tid] = be[tid];

    prefetch_tile(sm + W0S_OFF, sS, dS, ea, srcp, dstp, blockIdx.x * 128, tid, pol);
    cpa_commit();
    __syncthreads();

    int c8 = tid & 7, rq = tid >> 3;
    int j0 = c8 * 4, j1 = 32 + c8 * 4;
    u64 biasv[4] = { pack2(beS[j0], beS[j0 + 1]), pack2(beS[j0 + 2], beS[j0 + 3]),
                     pack2(beS[j1], beS[j1 + 1]), pack2(beS[j1 + 2], beS[j1 + 3]) };

    float ssum[8], sssq[8];
    #pragma unroll
    for (int i = 0; i < 8; i++) { ssum[i] = 0.0f; sssq[i] = 0.0f; }

    int buf = 0;
    for (int tile = blockIdx.x; tile < ETILES; tile += gridDim.x) {
        cpa_wait0();
        __syncthreads();
        float* w0c = sm + W0S_OFF + buf * W0S_STRIDE;
        int* sC = sS + buf * 128;
        int* dC = dS + buf * 128;
        int base = tile * 128;

        // ---- early gather for row rr=0 (hidden under GEMV) ----
        int s_cur = sC[rq], d_cur = dC[rq];
        const float* x3p = g_x3 + (size_t)s_cur * 64;
        const float* x24p = g_x24 + (size_t)d_cur * 128;
        float4 p0 = *(const float4*)(x3p + j0);
        float4 p1 = *(const float4*)(x3p + j1);
        float4 p2 = *(const float4*)(x24p + j0);
        float4 p3 = *(const float4*)(x24p + j1);
        float4 p4 = *(const float4*)(x24p + 64 + j0);
        float4 p5 = *(const float4*)(x24p + 64 + j1);

        // ---- issue next tile's prefetch (overlaps GEMV) ----
        int ntile = tile + gridDim.x;
        if (ntile < ETILES)
            prefetch_tile(sm + W0S_OFF + (buf ^ 1) * W0S_STRIDE,
                          sS + (buf ^ 1) * 128, dS + (buf ^ 1) * 128,
                          ea, srcp, dstp, ntile * 128, tid, pol);
        cpa_commit();

        // ---- GEMV: w1 = w0 @ We^T + be ----
        u64 acc[4][4];
        #pragma unroll
        for (int rr = 0; rr < 4; rr++) {
            acc[rr][0] = biasv[0]; acc[rr][1] = biasv[1];
            acc[rr][2] = biasv[2]; acc[rr][3] = biasv[3];
        }
        #pragma unroll
        for (int k0 = 0; k0 < 64; k0 += 4) {
            float w0r[4][4];
            #pragma unroll
            for (int rr = 0; rr < 4; rr++) {
                float4 a = *(const float4*)&w0c[(rq + 32 * rr) * 68 + k0];
                w0r[rr][0] = a.x; w0r[rr][1] = a.y; w0r[rr][2] = a.z; w0r[rr][3] = a.w;
            }
            #pragma unroll
            for (int kk = 0; kk < 4; kk++) {
                int k = k0 + kk;
                ulonglong2 wa = *(const ulonglong2*)&WtS[k * 64 + j0];
                ulonglong2 wb = *(const ulonglong2*)&WtS[k * 64 + j1];
                #pragma unroll
                for (int rr = 0; rr < 4; rr++) {
                    u64 av = bcast2(w0r[rr][kk]);
                    fma2(acc[rr][0], av, wa.x); fma2(acc[rr][1], av, wa.y);
                    fma2(acc[rr][2], av, wb.x); fma2(acc[rr][3], av, wb.y);
                }
            }
        }

        // ---- combine: software-pipelined over the 4 rows (1-deep) ----
        #pragma unroll
        for (int rr = 0; rr < 4; rr++) {
            int row = rq + 32 * rr;
            float4 x3a = p0, x3b = p1, x2a = p2, x2b = p3, x4a = p4, x4b = p5;
            int s_use = s_cur;
            if (rr < 3) {
                int nrow = row + 32;
                s_cur = sC[nrow]; d_cur = dC[nrow];
                const float* nx3 = g_x3 + (size_t)s_cur * 64;
                const float* nx24 = g_x24 + (size_t)d_cur * 128;
                p0 = *(const float4*)(nx3 + j0);
                p1 = *(const float4*)(nx3 + j1);
                p2 = *(const float4*)(nx24 + j0);
                p3 = *(const float4*)(nx24 + j1);
                p4 = *(const float4*)(nx24 + 64 + j0);
                p5 = *(const float4*)(nx24 + 64 + j1);
            }

            float2 w1_0 = unpack2(acc[rr][0]), w1_1 = unpack2(acc[rr][1]);
            float2 w1_2 = unpack2(acc[rr][2]), w1_3 = unpack2(acc[rr][3]);
            float tv[8];
            tv[0] = w1_0.x + x3a.x + x4a.x;
            tv[1] = w1_0.y + x3a.y + x4a.y;
            tv[2] = w1_1.x + x3a.z + x4a.z;
            tv[3] = w1_1.y + x3a.w + x4a.w;
            tv[4] = w1_2.x + x3b.x + x4b.x;
            tv[5] = w1_2.y + x3b.y + x4b.y;
            tv[6] = w1_3.x + x3b.z + x4b.z;
            tv[7] = w1_3.y + x3b.w + x4b.w;
            size_t eb = (size_t)(base + row) * 64;
            // fp16 store: 8 floats -> 4 half2 -> two 8B stores
            __half2 ha = __floats2half2_rn(tv[0], tv[1]);
            __half2 hb = __floats2half2_rn(tv[2], tv[3]);
            __half2 hc = __floats2half2_rn(tv[4], tv[5]);
            __half2 hd = __floats2half2_rn(tv[6], tv[7]);
            st8_cs(&g_t[eb + j0], *(unsigned*)&ha, *(unsigned*)&hb);
            st8_cs(&g_t[eb + j1], *(unsigned*)&hc, *(unsigned*)&hd);
            #pragma unroll
            for (int i = 0; i < 8; i++) {
                ssum[i] += tv[i];
                sssq[i] = fmaf(tv[i], tv[i], sssq[i]);
            }
            float4 wva = *(const float4*)&w0c[row * 68 + j0];
            float4 wvb = *(const float4*)&w0c[row * 68 + j1];
            float* sp = g_sums + (size_t)s_use * 64;
            red4(sp + j0, sigmoidf(wva.x) * x2a.x, sigmoidf(wva.y) * x2a.y,
                          sigmoidf(wva.z) * x2a.z, sigmoidf(wva.w) * x2a.w);
            red4(sp + j1, sigmoidf(wvb.x) * x2b.x, sigmoidf(wvb.y) * x2b.y,
                          sigmoidf(wvb.z) * x2b.z, sigmoidf(wvb.w) * x2b.w);
            if (c8 == 0) atomicAdd(&g_cnt[s_use], 1.0f);
        }
        buf ^= 1;
    }

    // ---- flush BN stats: warp shfl -> smem block reduction -> 128 atomics/block ----
    #pragma unroll
    for (int i = 0; i < 8; i++) {
        ssum[i] += __shfl_xor_sync(0xffffffffu, ssum[i], 8);
        ssum[i] += __shfl_xor_sync(0xffffffffu, ssum[i], 16);
        sssq[i] += __shfl_xor_sync(0xffffffffu, sssq[i], 8);
        sssq[i] += __shfl_xor_sync(0xffffffffu, sssq[i], 16);
    }
    __syncthreads();               // main loop done in all warps; WtS region now reusable
    float* redb = sm;              // [8 warps][128 stats]
    int warp = tid >> 5, lane = tid & 31;
    if ((lane & 24) == 0) {        // lanes 0..7: hold the 8 col-values for this c8
        #pragma unroll
        for (int i = 0; i < 8; i++) {
            int col = (i < 4) ? (j0 + i) : (j1 + i - 4);
            redb[warp * 128 + col] = ssum[i];
            redb[warp * 128 + 64 + col] = sssq[i];
        }
    }
    __syncthreads();
    if (tid < 128) {
        float v = 0.0f;
        #pragma unroll
        for (int w = 0; w < 8; w++) v += redb[w * 128 + tid];
        atomicAdd(&g_estat[tid], v);
    }
}

// ------------------- kernel 4: node pre-BN + stats (smem-reduced atomics) -------------------
#define NS_BLOCKS 512
__global__ void node_stats() {
    __shared__ float redb[8 * 128];
    int tid = threadIdx.x;
    int t = blockIdx.x * 256 + tid;
    int c = (tid & 15) * 4;
    int stride = (NS_BLOCKS * 256) >> 4;
    float s0 = 0, s1 = 0, s2 = 0, s3 = 0, q0 = 0, q1 = 0, q2 = 0, q3 = 0;
    for (int n = t >> 4; n < N_NODES; n += stride) {
        size_t off = (size_t)n * 64 + c;
        float4 a = *(const float4*)&g_x1[off];
        float4 g = *(const float4*)&g_sums[off];
        float inv = 1.0f / fmaxf(g_cnt[n], 1.0f);
        float4 y;
        y.x = fmaf(g.x, inv, a.x);
        y.y = fmaf(g.y, inv, a.y);
        y.z = fmaf(g.z, inv, a.z);
        y.w = fmaf(g.w, inv, a.w);
        *(float4*)&g_y[off] = y;
        s0 += y.x; q0 = fmaf(y.x, y.x, q0);
        s1 += y.y; q1 = fmaf(y.y, y.y, q1);
        s2 += y.z; q2 = fmaf(y.z, y.z, q2);
        s3 += y.w; q3 = fmaf(y.w, y.w, q3);
    }
    s0 += __shfl_xor_sync(0xffffffffu, s0, 16);
    s1 += __shfl_xor_sync(0xffffffffu, s1, 16);
    s2 += __shfl_xor_sync(0xffffffffu, s2, 16);
    s3 += __shfl_xor_sync(0xffffffffu, s3, 16);
    q0 += __shfl_xor_sync(0xffffffffu, q0, 16);
    q1 += __shfl_xor_sync(0xffffffffu, q1, 16);
    q2 += __shfl_xor_sync(0xffffffffu, q2, 16);
    q3 += __shfl_xor_sync(0xffffffffu, q3, 16);
    int warp = tid >> 5, lane = tid & 31;
    if (lane < 16) {
        redb[warp * 128 + c + 0] = s0;
        redb[warp * 128 + c + 1] = s1;
        redb[warp * 128 + c + 2] = s2;
        redb[warp * 128 + c + 3] = s3;
        redb[warp * 128 + 64 + c + 0] = q0;
        redb[warp * 128 + 64 + c + 1] = q1;
        redb[warp * 128 + 64 + c + 2] = q2;
        redb[warp * 128 + 64 + c + 3] = q3;
    }
    __syncthreads();
    if (tid < 128) {
        float v = 0.0f;
        #pragma unroll
        for (int w = 0; w < 8; w++) v += redb[w * 128 + tid];
        atomicAdd(&g_nstat[tid], v);
    }
}

// ------------------- kernel 5: fused BN + SiLU + residual -------------------
#define APPLY_NODE_BLOCKS 512
#define APPLY_EDGE_BLOCKS 4096
__global__ void apply_fused(const float* __restrict__ x, const float* __restrict__ ea,
                            const float* __restrict__ vg, const float* __restrict__ vb,
                            const float* __restrict__ eg, const float* __restrict__ eb,
                            float* __restrict__ out) {
    bool isEdge = blockIdx.x >= APPLY_NODE_BLOCKS;
    int bid     = isEdge ? (blockIdx.x - APPLY_NODE_BLOCKS) : blockIdx.x;
    const float* stat  = isEdge ? g_estat : g_nstat;
    float invRows = isEdge ? (1.0f / (float)N_EDGES) : (1.0f / (float)N_NODES);
    const float* gamma = isEdge ? eg : vg;
    const float* beta  = isEdge ? eb : vb;

    int t = bid * blockDim.x + threadIdx.x;
    int c = (t & 15) * 4;
    float A[4], B[4];
    #pragma unroll
    for (int i = 0; i < 4; i++) {
        float m = stat[c + i] * invRows;
        float var = stat[64 + c + i] * invRows - m * m;
        float rs = rsqrtf(var + 1e-5f);
        float gs = gamma[c + i] * rs;
        A[i] = gs;
        B[i] = fmaf(-m, gs, beta[c + i]);
    }
    if (!isEdge) {
        int stride = (APPLY_NODE_BLOCKS * 256) >> 4;
        for (int r = t >> 4; r < N_NODES; r += stride) {
            size_t off = (size_t)r * 64 + c;
            float4 y = __ldcs((const float4*)(g_y + off));
            float4 xv = __ldcs((const float4*)(x + off));
            float z0 = fmaf(y.x, A[0], B[0]);
            float z1 = fmaf(y.y, A[1], B[1]);
            float z2 = fmaf(y.z, A[2], B[2]);
            float z3 = fmaf(y.w, A[3], B[3]);
            float4 o;
            o.x = xv.x + z0 * sigmoidf(z0);
            o.y = xv.y + z1 * sigmoidf(z1);
            o.z = xv.z + z2 * sigmoidf(z2);
            o.w = xv.w + z3 * sigmoidf(z3);
            __stcs((float4*)(out + off), o);
        }
    } else {
        float* ob = out + (size_t)N_NODES * DD;
        int stride = (APPLY_EDGE_BLOCKS * 256) >> 4;
        for (int r = t >> 4; r < N_EDGES; r += stride) {
            size_t off = (size_t)r * 64 + c;
            uint2 u = __ldcs((const uint2*)(g_t + off));
            __half2 h0 = *(__half2*)&u.x;
            __half2 h1 = *(__half2*)&u.y;
            float2 y01 = __half22float2(h0);
            float2 y23 = __half22float2(h1);
            float4 xv = __ldcs((const float4*)(ea + off));
            float z0 = fmaf(y01.x, A[0], B[0]);
            float z1 = fmaf(y01.y, A[1], B[1]);
            float z2 = fmaf(y23.x, A[2], B[2]);
            float z3 = fmaf(y23.y, A[3], B[3]);
            float4 o;
            o.x = xv.x + z0 * sigmoidf(z0);
            o.y = xv.y + z1 * sigmoidf(z1);
            o.z = xv.z + z2 * sigmoidf(z2);
            o.w = xv.w + z3 * sigmoidf(z3);
            __stcs((float4*)(ob + off), o);
        }
    }
}

// ------------------- launch -------------------
extern "C" void kernel_launch(void* const* d_in, const int* in_sizes, int n_in,
                              void* d_out, int out_size) {
    const float* x   = (const float*)d_in[0];
    const float* ea  = (const float*)d_in[1];
    const float* W1  = (const float*)d_in[2];
    const float* b1  = (const float*)d_in[3];
    const float* W2  = (const float*)d_in[4];
    const float* b2  = (const float*)d_in[5];
    const float* W3  = (const float*)d_in[6];
    const float* b3  = (const float*)d_in[7];
    const float* W4  = (const float*)d_in[8];
    const float* b4  = (const float*)d_in[9];
    const float* We  = (const float*)d_in[10];
    const float* be  = (const float*)d_in[11];
    const float* vg  = (const float*)d_in[12];
    const float* vb  = (const float*)d_in[13];
    const float* eg  = (const float*)d_in[14];
    const float* ebt = (const float*)d_in[15];
    const int*   ei  = (const int*)d_in[16];
    const int* srcp = ei;
    const int* dstp = ei + N_EDGES;
    float* out = (float*)d_out;

    cudaFuncSetAttribute(node_gemm, cudaFuncAttributeMaxDynamicSharedMemorySize, NODE_SMEM);
    cudaFuncSetAttribute(edge_pass1, cudaFuncAttributeMaxDynamicSharedMemorySize, EDGE_SMEM);

    prepack<<<16, 256>>>(W1, W2, W3, W4, We, b1, b2, b3, b4);
    node_gemm<<<296, 256, NODE_SMEM>>>(x);
    edge_pass1<<<296, 256, EDGE_SMEM>>>(ea, srcp, dstp, be);
    node_stats<<<NS_BLOCKS, 256>>>();
    apply_fused<<<APPLY_NODE_BLOCKS + APPLY_EDGE_BLOCKS, 256>>>(x, ea, vg, vb, eg, ebt, out);
}